// round 10
// baseline (speedup 1.0000x reference)
#include <cuda_runtime.h>
#include <math.h>

// Problem constants
#define BB    128
#define TT    2048
#define DIN   32
#define HH    256
#define G4    1024          // 4*H
#define KK    288           // H + DIN (input projection folded into recurrence)
#define NBLK  128           // persistent recurrence blocks (1/SM, co-resident)
#define MPB   8             // batch rows per block   (16 groups)
#define NPB   32            // h-cols per block       (8 slices)
#define JPB   128           // gate cols per block = 4*NPB
#define NGRP  16            // batch groups
#define HS    10            // h_s row stride (floats): 8B-aligned pairs
#define KPW   36            // k per k-slice (8 slices * 36 = 288)
#define NTH   512           // 16 warps = 8 k-slices x 2 j-halves

// -------- static device scratch (no allocation allowed) --------
__device__ float    g_Wcomb[G4 * DIN];      // W_ih @ W_in   [1024][32]
__device__ float    g_bias[G4];             // b_ih + b_hh + W_ih @ b_in
__device__ float    g_h[2][BB][HH];         // double-buffered LSTM hidden state
__device__ float    g_emaA[BB * 32 * HH];
__device__ float    g_emaP[BB * 32 * HH];
__device__ float    g_ema_last[BB * HH];
__device__ unsigned g_cnt[NGRP * 32];       // per-group arrival counters (128B apart)

// ---------------- asm / math helpers -----------------------------------------
__device__ __forceinline__ unsigned ld_acq(const unsigned* p) {
    unsigned v;
    asm volatile("ld.acquire.gpu.global.u32 %0, [%1];" : "=r"(v) : "l"(p));
    return v;
}
__device__ __forceinline__ void red_add_release(unsigned* p, unsigned v) {
    asm volatile("red.release.gpu.global.add.u32 [%0], %1;" :: "l"(p), "r"(v) : "memory");
}
__device__ __forceinline__ float fsig(float x) {          // fast sigmoid
    return __fdividef(1.0f, 1.0f + __expf(-x));
}
__device__ __forceinline__ float ftanh(float x) {         // fast tanh
    return 1.0f - __fdividef(2.0f, __expf(2.0f * x) + 1.0f);
}
__device__ __forceinline__ unsigned long long dup2(float a) {
    unsigned long long r;
    asm("mov.b64 %0, {%1, %1};" : "=l"(r) : "f"(a));
    return r;
}
__device__ __forceinline__ void ffma2(unsigned long long& d,
                                      unsigned long long a, unsigned long long b) {
    asm("fma.rn.f32x2 %0, %1, %2, %0;" : "+l"(d) : "l"(a), "l"(b));
}
__device__ __forceinline__ void unpk(unsigned long long v, float& lo, float& hi) {
    asm("mov.b64 {%0, %1}, %2;" : "=f"(lo), "=f"(hi) : "l"(v));
}

// ---------------- prep: W_comb, fused bias, zero h(0), zero counters ---------
__global__ void __launch_bounds__(256)
prep_kernel(const float* __restrict__ W_in, const float* __restrict__ b_in,
            const float* __restrict__ W_ih, const float* __restrict__ b_ih,
            const float* __restrict__ b_hh)
{
    int idx = blockIdx.x * 256 + threadIdx.x;
    if (idx < NGRP * 32) g_cnt[idx] = 0u;
    if (idx < G4 * DIN) {
        int r = idx >> 5;          // gate row 0..1023
        int c = idx & 31;          // input col 0..31
        float s = 0.0f;
        for (int k = 0; k < HH; k++)
            s = fmaf(W_ih[r * HH + k], W_in[k * DIN + c], s);
        g_Wcomb[idx] = s;
        ((float*)g_h)[idx] = 0.0f;             // zero buffer 0 = h(0) (same 32768 extent)
    } else if (idx < G4 * DIN + G4) {
        int r = idx - G4 * DIN;
        float s = b_ih[r] + b_hh[r];
        for (int k = 0; k < HH; k++)
            s = fmaf(W_ih[r * HH + k], b_in[k], s);
        g_bias[r] = s;
    }
}

// ---------------- EMA: 64-step chunk -> (A, P) with out = A + P*prev ---------
__global__ void __launch_bounds__(256)
ema_scan_kernel(const float* __restrict__ x,
                const float* __restrict__ W_proj, const float* __restrict__ b_proj,
                const float* __restrict__ W_gate, const float* __restrict__ b_gate)
{
    const int b  = blockIdx.x >> 5;
    const int ch = blockIdx.x & 31;
    const int h  = threadIdx.x;

    __shared__ __align__(16) float x_s[64][DIN];
    for (int i = h; i < 64 * DIN; i += 256) {
        int tt = i >> 5, kk = i & 31;
        x_s[tt][kk] = x[((size_t)b * TT + ch * 64 + tt) * DIN + kk];
    }
    float wz[DIN], wg[DIN];
#pragma unroll
    for (int k = 0; k < DIN; k++) {
        wz[k] = W_proj[h * DIN + k];
        wg[k] = W_gate[h * DIN + k];
    }
    const float bz = b_proj[h], bgv = b_gate[h];
    __syncthreads();

    float A = 0.0f, P = 1.0f;
    for (int tt = 0; tt < 64; tt++) {
        float z = bz, gp = bgv;
#pragma unroll
        for (int q = 0; q < 8; q++) {
            float4 xq = *(const float4*)&x_s[tt][q * 4];
            z  = fmaf(wz[q*4+0], xq.x, z);  z  = fmaf(wz[q*4+1], xq.y, z);
            z  = fmaf(wz[q*4+2], xq.z, z);  z  = fmaf(wz[q*4+3], xq.w, z);
            gp = fmaf(wg[q*4+0], xq.x, gp); gp = fmaf(wg[q*4+1], xq.y, gp);
            gp = fmaf(wg[q*4+2], xq.z, gp); gp = fmaf(wg[q*4+3], xq.w, gp);
        }
        float g  = fsig(gp);
        float om = 1.0f - g;
        A = fmaf(om, A, g * z);
        P *= om;
    }
    g_emaA[((size_t)b * 32 + ch) * HH + h] = A;
    g_emaP[((size_t)b * 32 + ch) * HH + h] = P;
}

__global__ void __launch_bounds__(256) ema_combine_kernel()
{
    const int b = blockIdx.x;
    const int h = threadIdx.x;
    float prev = 0.0f;
#pragma unroll 8
    for (int c = 0; c < 32; c++) {
        float A = g_emaA[((size_t)b * 32 + c) * HH + h];
        float P = g_emaP[((size_t)b * 32 + c) * HH + h];
        prev = fmaf(P, prev, A);
    }
    g_ema_last[b * HH + h] = prev;
}

// ---------------- persistent LSTM recurrence --------------------------------
// 128 blocks = 16 batch-groups x 8 h-slices. Sync scope = 8 blocks of a group.
// 16 warps = 8 k-slices x 2 j-halves. Warp (ks, jh): k in [36ks, 36ks+36),
// j in [64jh, 64jh+64), 2 j-cols per lane (permuted j = hc*4 + gi).
// Weights in registers: wreg[36][2] per thread (72 floats).
// SMEM: h_s[288][HS] staged h+x, red_s[64][128].
#define SMEM_FLOATS (KK*HS + 64*JPB)
#define SMEM_BYTES  (SMEM_FLOATS * 4)

__global__ void __launch_bounds__(NTH, 1)
recur_kernel(const float* __restrict__ x, const float* __restrict__ W_hh)
{
    extern __shared__ float sm[];
    float* h_s    = sm;                        // [288][HS]
    float* red_s  = h_s + KK * HS;             // [64][128]

    const int tid = threadIdx.x;
    const int bg  = blockIdx.x >> 3;
    const int m0  = bg * MPB;
    const int n0  = (blockIdx.x & 7) * NPB;

    const int w     = tid >> 5;
    const int lane  = tid & 31;
    const int ks    = w & 7;        // k-slice
    const int jh    = w >> 3;       // j-half (0/1)
    const int kbase = ks * KPW;
    const int j2    = jh * 64 + lane * 2;   // this thread's first j col
    const int m_ld  = w & 7;        // staging: row (both halves stage same row)
    const int mg    = tid >> 5;     // gate-phase batch row (tid<256)
    const int hc    = tid & 31;     // gate-phase h-col

    // one-time: load weight slice into registers.
    // wreg[kk][jj] = W[r][k], r = gi*256+n0+hcw for j = j2+jj (gi=j&3, hcw=j>>2)
    float wreg[KPW][2];
#pragma unroll
    for (int kk = 0; kk < KPW; kk++) {
        const int k = kbase + kk;
#pragma unroll
        for (int jj = 0; jj < 2; jj++) {
            const int j  = j2 + jj;
            const int r  = ((j & 3) << 8) + n0 + (j >> 2);
            wreg[kk][jj] = (k < HH) ? W_hh[r * HH + k]
                                    : g_Wcomb[r * DIN + (k - HH)];
        }
    }
    // bias quad for gate phase (i,f,g,o at column n0+hc); valid for tid<256
    const float4 bv = make_float4(g_bias[0 * 256 + n0 + hc],
                                  g_bias[1 * 256 + n0 + hc],
                                  g_bias[2 * 256 + n0 + hc],
                                  g_bias[3 * 256 + n0 + hc]);
    float c_val = 0.0f;

    unsigned* cnt = &g_cnt[bg * 32];

    // h(0) zeros staged by prep_kernel (kernel-order visibility)
    for (int t = 0; t < TT; t++) {
        const int p = t & 1;
        // x_t prefetch (upper warps own x staging)
        float xv = 0.0f;
        if (jh == 1)
            xv = __ldg(&x[((size_t)(m0 + m_ld) * TT + t) * DIN + lane]);

        // stage h(t) from L2: warp (ks,jh) stages row m_ld, k-half jh
        {
            const float* hb = &g_h[p][m0 + m_ld][0];
            const int koff = jh * 128;
#pragma unroll
            for (int q = 0; q < 4; q++) {
                const int k = koff + lane + 32 * q;
                h_s[k * HS + m_ld] = __ldcg(&hb[k]);
            }
            if (jh == 1)
                h_s[(HH + lane) * HS + m_ld] = xv;
        }
        __syncthreads();

        // matvec: f32x2 over batch-row pairs, W in registers, 2 j-cols/lane
        {
            unsigned long long acc2[4][2];     // [m-pair][jj]
#pragma unroll
            for (int mp = 0; mp < 4; mp++) { acc2[mp][0] = 0ull; acc2[mp][1] = 0ull; }

#pragma unroll
            for (int kk = 0; kk < KPW; kk++) {
                const int k = kbase + kk;
                const unsigned long long hp[4] = {
                    *(const unsigned long long*)&h_s[k * HS + 0],
                    *(const unsigned long long*)&h_s[k * HS + 2],
                    *(const unsigned long long*)&h_s[k * HS + 4],
                    *(const unsigned long long*)&h_s[k * HS + 6] };
                const unsigned long long w0 = dup2(wreg[kk][0]);
                const unsigned long long w1 = dup2(wreg[kk][1]);
#pragma unroll
                for (int mp = 0; mp < 4; mp++) {
                    ffma2(acc2[mp][0], hp[mp], w0);
                    ffma2(acc2[mp][1], hp[mp], w1);
                }
            }

            float a[MPB][2];
#pragma unroll
            for (int mp = 0; mp < 4; mp++) {
                unpk(acc2[mp][0], a[2 * mp][0], a[2 * mp + 1][0]);
                unpk(acc2[mp][1], a[2 * mp][1], a[2 * mp + 1][1]);
            }
#pragma unroll
            for (int m = 0; m < MPB; m++)
                *(float2*)&red_s[(ks * MPB + m) * JPB + j2] =
                    make_float2(a[m][0], a[m][1]);
        }
        __syncthreads();

        // gate phase (tid < 256): thread (mg, hc) reduces 8 k-partials (float4)
        if (tid < 256) {
            float4 sv = bv;
#pragma unroll
            for (int tk = 0; tk < 8; tk++) {
                const float4 r4 =
                    *(const float4*)&red_s[(tk * MPB + mg) * JPB + hc * 4];
                sv.x += r4.x; sv.y += r4.y; sv.z += r4.z; sv.w += r4.w;
            }
            const float ig = fsig(sv.x);
            const float fg = fsig(sv.y);
            const float gg = ftanh(sv.z);
            const float og = fsig(sv.w);
            c_val = fmaf(fg, c_val, ig * gg);
            g_h[p ^ 1][m0 + mg][n0 + hc] = og * ftanh(c_val);
        }

        // scoped group barrier: release-arrive by tid0, acquire-spin, no resets.
        __syncthreads();
        if (tid == 0) {
            red_add_release(cnt, 1u);
            const unsigned tgt = 8u * (unsigned)(t + 1);
            while (ld_acq(cnt) < tgt) { }
        }
        __syncthreads();
    }
    // h_last = h(2048) lives in g_h[0]
}

// ---------------- head: concat -> LayerNorm -> GELU(erf) MLP -> out ---------
__global__ void __launch_bounds__(256)
head_kernel(const float* __restrict__ ln_scale, const float* __restrict__ ln_bias,
            const float* __restrict__ W_h1, const float* __restrict__ b_h1,
            const float* __restrict__ W_h2, const float* __restrict__ b_h2,
            float* __restrict__ out)
{
    __shared__ __align__(16) float ns[512];
    __shared__ float red[32];
    __shared__ float mu_s, rv_s;

    const int b = blockIdx.x;
    const int tid = threadIdx.x;

    const float v0 = g_h[0][b][tid];
    const float v1 = g_ema_last[b * HH + tid];

    float s = v0 + v1, sq = v0 * v0 + v1 * v1;
#pragma unroll
    for (int o = 16; o; o >>= 1) {
        s  += __shfl_down_sync(0xffffffffu, s,  o);
        sq += __shfl_down_sync(0xffffffffu, sq, o);
    }
    if ((tid & 31) == 0) { red[tid >> 5] = s; red[8 + (tid >> 5)] = sq; }
    __syncthreads();
    if (tid == 0) {
        float ts = 0.f, tq = 0.f;
        for (int i = 0; i < 8; i++) { ts += red[i]; tq += red[8 + i]; }
        float mu = ts / 512.0f;
        mu_s = mu;
        rv_s = rsqrtf(tq / 512.0f - mu * mu + 1e-5f);
    }
    __syncthreads();
    const float mu = mu_s, ri = rv_s;
    ns[tid]       = fmaf((v0 - mu) * ri, ln_scale[tid],       ln_bias[tid]);
    ns[tid + 256] = fmaf((v1 - mu) * ri, ln_scale[tid + 256], ln_bias[tid + 256]);
    __syncthreads();

    float acc = b_h1[tid];
    const float4* wr = (const float4*)(W_h1 + (size_t)tid * 512);
#pragma unroll 8
    for (int q = 0; q < 128; q++) {
        float4 w = wr[q];
        float4 n = *(const float4*)&ns[q * 4];
        acc = fmaf(w.x, n.x, acc); acc = fmaf(w.y, n.y, acc);
        acc = fmaf(w.z, n.z, acc); acc = fmaf(w.w, n.w, acc);
    }
    float g1 = 0.5f * acc * (1.0f + erff(acc * 0.70710678118654752f));
    float p = g1 * W_h2[tid];
#pragma unroll
    for (int o = 16; o; o >>= 1) p += __shfl_down_sync(0xffffffffu, p, o);
    if ((tid & 31) == 0) red[16 + (tid >> 5)] = p;
    __syncthreads();
    if (tid == 0) {
        float tsum = b_h2[0];
        for (int i = 0; i < 8; i++) tsum += red[16 + i];
        out[b] = tsum;
    }
}

// ---------------- launch ----------------------------------------------------
extern "C" void kernel_launch(void* const* d_in, const int* in_sizes, int n_in,
                              void* d_out, int out_size)
{
    (void)in_sizes; (void)n_in; (void)out_size;
    const float* x        = (const float*)d_in[0];
    const float* W_in     = (const float*)d_in[1];
    const float* b_in     = (const float*)d_in[2];
    const float* W_ih     = (const float*)d_in[3];
    const float* W_hh     = (const float*)d_in[4];
    const float* b_ih     = (const float*)d_in[5];
    const float* b_hh     = (const float*)d_in[6];
    const float* W_proj   = (const float*)d_in[7];
    const float* b_proj   = (const float*)d_in[8];
    const float* W_gate   = (const float*)d_in[9];
    const float* b_gate   = (const float*)d_in[10];
    const float* ln_scale = (const float*)d_in[11];
    const float* ln_bias  = (const float*)d_in[12];
    const float* W_h1     = (const float*)d_in[13];
    const float* b_h1     = (const float*)d_in[14];
    const float* W_h2     = (const float*)d_in[15];
    const float* b_h2     = (const float*)d_in[16];
    float* out = (float*)d_out;

    cudaFuncSetAttribute(recur_kernel,
                         cudaFuncAttributeMaxDynamicSharedMemorySize, SMEM_BYTES);

    prep_kernel<<<132, 256>>>(W_in, b_in, W_ih, b_ih, b_hh);
    recur_kernel<<<NBLK, NTH, SMEM_BYTES>>>(x, W_hh);
    ema_scan_kernel<<<BB * 32, 256>>>(x, W_proj, b_proj, W_gate, b_gate);
    ema_combine_kernel<<<BB, 256>>>();
    head_kernel<<<BB, 256>>>(ln_scale, ln_bias, W_h1, b_h1, W_h2, b_h2, out);
}